// round 7
// baseline (speedup 1.0000x reference)
#include <cuda_runtime.h>
#include <cuda_fp16.h>
#include <math.h>

#define B 64
#define J 2048
#define N 32
#define D 16
#define ND 512
#define EPS 1e-7f

__device__ __align__(16) __half g_Wh[(size_t)N * J * D * 16];  // 33.5 MiB fp16 W
__device__ __align__(16) __half g_xh[(size_t)B * J * 16];      // 4.2 MiB fp16 x
__device__ __align__(16) float g_spart[3][B * ND];             // s accum [b][n*16+d]

// ---- helpers --------------------------------------------------------------
static __device__ __forceinline__ unsigned long long pk2(float a, float b) {
    unsigned long long v;
    asm("mov.b64 %0, {%1, %2};" : "=l"(v) : "f"(a), "f"(b));
    return v;
}
static __device__ __forceinline__ float2 upk2(unsigned long long v) {
    float2 f;
    asm("mov.b64 {%0, %1}, %2;" : "=f"(f.x), "=f"(f.y) : "l"(v));
    return f;
}
static __device__ __forceinline__ void fma2(unsigned long long& d,
                                            unsigned long long a,
                                            unsigned long long b) {
    asm("fma.rn.f32x2 %0, %1, %2, %0;" : "+l"(d) : "l"(a), "l"(b));
}
static __device__ __forceinline__ void redv2(float* p, float a, float b) {
    asm volatile("red.global.add.v2.f32 [%0], {%1, %2};"
                 :: "l"(p), "f"(a), "f"(b) : "memory");
}
static __device__ __forceinline__ void mma16816(
    float& d0, float& d1, float& d2, float& d3,
    unsigned a0, unsigned a1, unsigned a2, unsigned a3,
    unsigned b0, unsigned b1,
    float c0, float c1, float c2, float c3) {
    asm volatile(
        "mma.sync.aligned.m16n8k16.row.col.f32.f16.f16.f32 "
        "{%0,%1,%2,%3},{%4,%5,%6,%7},{%8,%9},{%10,%11,%12,%13};"
        : "=f"(d0), "=f"(d1), "=f"(d2), "=f"(d3)
        : "r"(a0), "r"(a1), "r"(a2), "r"(a3), "r"(b0), "r"(b1),
          "f"(c0), "f"(c1), "f"(c2), "f"(c3));
}

// ---------------------------------------------------------------------------
__global__ void cvt_x_zero_kernel(const float4* __restrict__ src) {
    int t = blockIdx.x * blockDim.x + threadIdx.x;  // < 524288
    float4 f = src[t];
    __half2 h0 = __floats2half2_rn(f.x, f.y);
    __half2 h1 = __floats2half2_rn(f.z, f.w);
    uint2 o;
    o.x = *reinterpret_cast<unsigned*>(&h0);
    o.y = *reinterpret_cast<unsigned*>(&h1);
    reinterpret_cast<uint2*>(g_xh)[t] = o;
    if (t < 3 * B * ND) ((float*)g_spart)[t] = 0.0f;
}

// ---------------------------------------------------------------------------
// k_s0cvt: stream W fp32, convert->fp16 (store g_Wh), mma-accumulate s0.
// grid 256 (jtile 8), 256 threads / 8 warps.
// ---------------------------------------------------------------------------
__global__ void __launch_bounds__(256, 1)
k_s0cvt_kernel(const float* __restrict__ Wf) {
    const int tid = threadIdx.x;
    const int w = tid >> 5;
    const int lane = tid & 31;
    const int gid = lane >> 2;
    const int tig = lane & 3;

    float C[8][4][4];
#pragma unroll
    for (int nt = 0; nt < 8; ++nt)
#pragma unroll
        for (int mi = 0; mi < 4; ++mi)
#pragma unroll
            for (int e = 0; e < 4; ++e) C[nt][mi][e] = 0.0f;

    for (int jj = 0; jj < 8; ++jj) {
        const int j = blockIdx.x * 8 + jj;

        float2 F0[8], F1[8];
#pragma unroll
        for (int nt = 0; nt < 8; ++nt) {
            const int r = 64 * w + 8 * nt + gid;
            const float* wp = Wf + ((size_t)((r >> 4) * J + j)) * 256 + ((r & 15) << 4);
            F0[nt] = *reinterpret_cast<const float2*>(wp + 2 * tig);
            F1[nt] = *reinterpret_cast<const float2*>(wp + 2 * tig + 8);
        }

        unsigned a[4][4];
#pragma unroll
        for (int mi = 0; mi < 4; ++mi) {
            const __half* x0 = g_xh + (((size_t)((mi * 16 + gid) * J + j)) << 4);
            const __half* x1 = g_xh + (((size_t)((mi * 16 + gid + 8) * J + j)) << 4);
            a[mi][0] = *reinterpret_cast<const unsigned*>(x0 + 2 * tig);
            a[mi][1] = *reinterpret_cast<const unsigned*>(x1 + 2 * tig);
            a[mi][2] = *reinterpret_cast<const unsigned*>(x0 + 2 * tig + 8);
            a[mi][3] = *reinterpret_cast<const unsigned*>(x1 + 2 * tig + 8);
        }

#pragma unroll
        for (int nt = 0; nt < 8; ++nt) {
            const int r = 64 * w + 8 * nt + gid;
            __half2 h0 = __floats2half2_rn(F0[nt].x, F0[nt].y);
            __half2 h1 = __floats2half2_rn(F1[nt].x, F1[nt].y);
            unsigned b0 = *reinterpret_cast<unsigned*>(&h0);
            unsigned b1 = *reinterpret_cast<unsigned*>(&h1);
            __half* op = g_Wh + ((size_t)((r >> 4) * J + j)) * 256 + ((r & 15) << 4);
            *reinterpret_cast<unsigned*>(op + 2 * tig) = b0;
            *reinterpret_cast<unsigned*>(op + 2 * tig + 8) = b1;
#pragma unroll
            for (int mi = 0; mi < 4; ++mi)
                mma16816(C[nt][mi][0], C[nt][mi][1], C[nt][mi][2], C[nt][mi][3],
                         a[mi][0], a[mi][1], a[mi][2], a[mi][3], b0, b1,
                         C[nt][mi][0], C[nt][mi][1], C[nt][mi][2], C[nt][mi][3]);
        }
    }

#pragma unroll
    for (int nt = 0; nt < 8; ++nt) {
        const int r = 64 * w + 8 * nt + 2 * tig;
#pragma unroll
        for (int mi = 0; mi < 4; ++mi) {
            const int brow = mi * 16 + gid;
            redv2(&g_spart[0][brow * ND + r], C[nt][mi][0], C[nt][mi][1]);
            redv2(&g_spart[0][(brow + 8) * ND + r], C[nt][mi][2], C[nt][mi][3]);
        }
    }
}

// ---------------------------------------------------------------------------
// Fused routing pass, 8-b blocks, 2 CTAs/SM.
// grid 592: bg = blockIdx.x & 7 (8 b), cid = blockIdx.x >> 3 (j chunk).
// Warp w: r in [64w, 64w+64) (n = 4w..4w+3). One barrier per j, parity ts,
// alternating A/B W-fragment prefetch.
// MODE 1: v = squash(s0/32); MODE 2: v = squash(s0/32)+squash(s1).
// ---------------------------------------------------------------------------
template <int MODE>
__global__ void __launch_bounds__(256, 2) route_fused_kernel() {
    __shared__ float ts[2][8][36];

    const int tid = threadIdx.x;
    const int w = tid >> 5;
    const int lane = tid & 31;
    const int gid = lane >> 2;
    const int tig = lane & 3;
    const int bg = blockIdx.x & 7;
    const int cid = blockIdx.x >> 3;  // 0..73

    int jstart, rounds;
    if (cid < 62) { jstart = 28 * cid; rounds = 28; }
    else { jstart = 1736 + 26 * (cid - 62); rounds = 26; }

    const int b = bg * 8 + gid;

    // --- prologue: squash(s) -> v in registers -----------------------------
    unsigned long long vr[4][2];
#pragma unroll
    for (int q = 0; q < 4; ++q) {
        const int n = 4 * w + q;
        float vx0 = 0.f, vy0 = 0.f, vx1 = 0.f, vy1 = 0.f;
#pragma unroll
        for (int it = 0; it < MODE; ++it) {
            const float pre = (it == 0) ? (1.0f / 32.0f) : 1.0f;
            const float* sp = &g_spart[it][(b * 32 + n) * 16];
            float2 f0 = *reinterpret_cast<const float2*>(sp + 2 * tig);
            float2 f1 = *reinterpret_cast<const float2*>(sp + 8 + 2 * tig);
            f0.x *= pre; f0.y *= pre; f1.x *= pre; f1.y *= pre;
            float p = f0.x * f0.x + f0.y * f0.y + f1.x * f1.x + f1.y * f1.y;
            p += __shfl_xor_sync(0xffffffffu, p, 1);
            p += __shfl_xor_sync(0xffffffffu, p, 2);
            p += EPS;
            float sc = sqrtf(p) / (1.0f + p);
            vx0 += sc * f0.x; vy0 += sc * f0.y;
            vx1 += sc * f1.x; vy1 += sc * f1.y;
        }
        vr[q][0] = pk2(vx0, vy0);
        vr[q][1] = pk2(vx1, vy1);
    }

    unsigned long long s2[8];
#pragma unroll
    for (int nt = 0; nt < 8; ++nt) s2[nt] = 0ull;

    unsigned A0[8], A1[8], B0[8], B1[8];
    unsigned long long p01[8];

#define LOADW(jv, d0, d1)                                                      \
    {                                                                          \
        const int jc_ = (jv) > (J - 1) ? (J - 1) : (jv);                       \
        _Pragma("unroll") for (int nt = 0; nt < 8; ++nt) {                     \
            const int r = 64 * w + 8 * nt + gid;                               \
            const __half* wp =                                                 \
                g_Wh + ((size_t)((r >> 4) * J + jc_)) * 256 + ((r & 15) << 4); \
            d0[nt] = __ldg(reinterpret_cast<const unsigned*>(wp + 2 * tig));   \
            d1[nt] = __ldg(reinterpret_cast<const unsigned*>(wp + 2 * tig + 8));\
        }                                                                      \
    }

#define PRODUCE(jv, c0, c1, n0, n1, par, DO_PF)                                \
    {                                                                          \
        const int j = (jv);                                                    \
        const __half* x0 = g_xh + (((size_t)(b * J + j)) << 4);                \
        const unsigned a0 = *reinterpret_cast<const unsigned*>(x0 + 2 * tig);  \
        const unsigned a2 = *reinterpret_cast<const unsigned*>(x0 + 2 * tig + 8);\
        _Pragma("unroll") for (int nt = 0; nt < 8; ++nt) {                     \
            float d0, d1, d2, d3;                                              \
            mma16816(d0, d1, d2, d3, a0, 0u, a2, 0u, c0[nt], c1[nt],           \
                     0.0f, 0.0f, 0.0f, 0.0f);                                  \
            p01[nt] = pk2(d0, d1);                                             \
        }                                                                      \
        if (DO_PF) LOADW(j + 1, n0, n1);                                       \
        float tv0[4];                                                          \
        _Pragma("unroll") for (int q = 0; q < 4; ++q) {                        \
            unsigned long long t2 = 0ull;                                      \
            fma2(t2, p01[2 * q], vr[q][0]);                                    \
            fma2(t2, p01[2 * q + 1], vr[q][1]);                                \
            float2 f = upk2(t2);                                               \
            float tt = f.x + f.y;                                              \
            tt += __shfl_xor_sync(0xffffffffu, tt, 1);                         \
            tt += __shfl_xor_sync(0xffffffffu, tt, 2);                         \
            tv0[q] = tt;                                                       \
        }                                                                      \
        float e0 = __expf(tig == 0 ? tv0[0] : tig == 1 ? tv0[1]                \
                                  : tig == 2 ? tv0[2] : tv0[3]);               \
        ts[par][gid][4 * w + tig] = e0;                                        \
    }

#define CONSUME(par)                                                           \
    {                                                                          \
        float4 sa0 = *reinterpret_cast<const float4*>(&ts[par][gid][tig * 8]); \
        float4 sa1 = *reinterpret_cast<const float4*>(&ts[par][gid][tig * 8 + 4]);\
        float SA = sa0.x + sa0.y + sa0.z + sa0.w + sa1.x + sa1.y + sa1.z + sa1.w;\
        SA += __shfl_xor_sync(0xffffffffu, SA, 1);                             \
        SA += __shfl_xor_sync(0xffffffffu, SA, 2);                             \
        float rA = __fdividef(1.0f, SA);                                       \
        float4 eA = *reinterpret_cast<const float4*>(&ts[par][gid][4 * w]);    \
        const float cAa[4] = {eA.x * rA, eA.y * rA, eA.z * rA, eA.w * rA};     \
        _Pragma("unroll") for (int nt = 0; nt < 8; ++nt) {                     \
            const int q = nt >> 1;                                             \
            fma2(s2[nt], pk2(cAa[q], cAa[q]), p01[nt]);                        \
        }                                                                      \
    }

    LOADW(jstart, A0, A1);
    for (int rd = 0; rd < rounds; rd += 2) {
        PRODUCE(jstart + rd, A0, A1, B0, B1, 0, 1);
        __syncthreads();
        CONSUME(0);
        PRODUCE(jstart + rd + 1, B0, B1, A0, A1, 1, (rd + 2 < rounds));
        __syncthreads();
        CONSUME(1);
    }
#undef PRODUCE
#undef CONSUME
#undef LOADW

    // flush s partials
#pragma unroll
    for (int nt = 0; nt < 8; ++nt) {
        const int r = 64 * w + 8 * nt + 2 * tig;
        float2 fa = upk2(s2[nt]);
        redv2(&g_spart[MODE][b * ND + r], fa.x, fa.y);
    }
}

// ---------------------------------------------------------------------------
__global__ void squash_out_kernel(float* __restrict__ out) {
    int t = blockIdx.x * blockDim.x + threadIdx.x;  // (b*32+n)
    const float* s = &g_spart[2][t * 16];
    float sv[16];
    float s2 = 0.0f;
#pragma unroll
    for (int d = 0; d < 16; ++d) {
        float val = s[d];
        sv[d] = val;
        s2 = fmaf(val, val, s2);
    }
    s2 += EPS;
    float sc = sqrtf(s2) / (1.0f + s2);
#pragma unroll
    for (int d = 0; d < 16; ++d) out[t * 16 + d] = sc * sv[d];
}

// ---------------------------------------------------------------------------
extern "C" void kernel_launch(void* const* d_in, const int* in_sizes, int n_in,
                              void* d_out, int out_size) {
    const float* x = (const float*)d_in[0];  // [B, J, 16]
    const float* W = (const float*)d_in[1];  // [N, J, D, 16]
    float* out = (float*)d_out;              // [B, N, D]

    cvt_x_zero_kernel<<<2048, 256>>>((const float4*)x);
    k_s0cvt_kernel<<<256, 256>>>(W);
    route_fused_kernel<1><<<592, 256>>>();
    route_fused_kernel<2><<<592, 256>>>();
    squash_out_kernel<<<16, 128>>>(out);
}

// round 8
// speedup vs baseline: 1.2728x; 1.2728x over previous
#include <cuda_runtime.h>
#include <cuda_fp16.h>
#include <math.h>

#define B 64
#define J 2048
#define N 32
#define D 16
#define ND 512
#define EPS 1e-7f

// Swizzled fragment storage (we define the layout):
// g_Wsw[(j*64 + w*8 + nt)*32 + lane] = uint2{b0,b1} for r = 64w+8nt+gid, tig
__device__ __align__(16) uint2 g_Wsw[(size_t)J * 64 * 32];   // 33.5 MiB
// g_xsw[(j*8 + bg)*32 + lane] = uint2{a0,a2} for b = bg*8+gid, tig
__device__ __align__(16) uint2 g_xsw[(size_t)J * 8 * 32];    // 4.2 MiB
__device__ __align__(16) float g_spart[3][B * ND];           // s accum [b][n*16+d]

// ---- helpers --------------------------------------------------------------
static __device__ __forceinline__ unsigned long long pk2(float a, float b) {
    unsigned long long v;
    asm("mov.b64 %0, {%1, %2};" : "=l"(v) : "f"(a), "f"(b));
    return v;
}
static __device__ __forceinline__ float2 upk2(unsigned long long v) {
    float2 f;
    asm("mov.b64 {%0, %1}, %2;" : "=f"(f.x), "=f"(f.y) : "l"(v));
    return f;
}
static __device__ __forceinline__ void fma2(unsigned long long& d,
                                            unsigned long long a,
                                            unsigned long long b) {
    asm("fma.rn.f32x2 %0, %1, %2, %0;" : "+l"(d) : "l"(a), "l"(b));
}
static __device__ __forceinline__ void redv2(float* p, float a, float b) {
    asm volatile("red.global.add.v2.f32 [%0], {%1, %2};"
                 :: "l"(p), "f"(a), "f"(b) : "memory");
}
static __device__ __forceinline__ void mma16816(
    float& d0, float& d1, float& d2, float& d3,
    unsigned a0, unsigned a1, unsigned a2, unsigned a3,
    unsigned b0, unsigned b1,
    float c0, float c1, float c2, float c3) {
    asm volatile(
        "mma.sync.aligned.m16n8k16.row.col.f32.f16.f16.f32 "
        "{%0,%1,%2,%3},{%4,%5,%6,%7},{%8,%9},{%10,%11,%12,%13};"
        : "=f"(d0), "=f"(d1), "=f"(d2), "=f"(d3)
        : "r"(a0), "r"(a1), "r"(a2), "r"(a3), "r"(b0), "r"(b1),
          "f"(c0), "f"(c1), "f"(c2), "f"(c3));
}

// ---------------------------------------------------------------------------
// cvt_x: build swizzled x fragments + zero spart.
// One thread per output uint2 (524288 total).
// ---------------------------------------------------------------------------
__global__ void cvt_x_zero_kernel(const float* __restrict__ x) {
    int o = blockIdx.x * blockDim.x + threadIdx.x;  // < 524288
    const int lane = o & 31;
    const int bg = (o >> 5) & 7;
    const int j = o >> 8;
    const int tig = lane & 3;
    const int gid = lane >> 2;
    const int b = bg * 8 + gid;

    const float* xp = x + ((size_t)(b * J + j) << 4);
    float2 f0 = *reinterpret_cast<const float2*>(xp + 2 * tig);
    float2 f1 = *reinterpret_cast<const float2*>(xp + 2 * tig + 8);
    __half2 h0 = __floats2half2_rn(f0.x, f0.y);
    __half2 h1 = __floats2half2_rn(f1.x, f1.y);
    uint2 out;
    out.x = *reinterpret_cast<unsigned*>(&h0);
    out.y = *reinterpret_cast<unsigned*>(&h1);
    g_xsw[o] = out;

    if (o < 3 * B * ND) ((float*)g_spart)[o] = 0.0f;
}

// ---------------------------------------------------------------------------
// k_s0cvt: stream W fp32 -> fp16 swizzled fragments (coalesced store),
// mma-accumulate s0. grid 256 (jtile 8), 256 thr / 8 warps.
// ---------------------------------------------------------------------------
__global__ void __launch_bounds__(256, 1)
k_s0cvt_kernel(const float* __restrict__ Wf) {
    const int tid = threadIdx.x;
    const int w = tid >> 5;
    const int lane = tid & 31;
    const int gid = lane >> 2;
    const int tig = lane & 3;

    float C[8][4][4];
#pragma unroll
    for (int nt = 0; nt < 8; ++nt)
#pragma unroll
        for (int mi = 0; mi < 4; ++mi)
#pragma unroll
            for (int e = 0; e < 4; ++e) C[nt][mi][e] = 0.0f;

    for (int jj = 0; jj < 8; ++jj) {
        const int j = blockIdx.x * 8 + jj;

        // W fp32 loads: per (w,nt) the warp covers a contiguous ~512B region
        float2 F0[8], F1[8];
#pragma unroll
        for (int nt = 0; nt < 8; ++nt) {
            const int r = 64 * w + 8 * nt + gid;
            const float* wp = Wf + ((size_t)((r >> 4) * J + j)) * 256 + ((r & 15) << 4);
            F0[nt] = *reinterpret_cast<const float2*>(wp + 2 * tig);
            F1[nt] = *reinterpret_cast<const float2*>(wp + 2 * tig + 8);
        }

        // x fragments: coalesced from g_xsw
        unsigned a[4][4];
#pragma unroll
        for (int mi = 0; mi < 4; ++mi) {
            uint2 xv0 = __ldg(&g_xsw[(size_t)(j * 8 + 2 * mi) * 32 + lane]);
            uint2 xv1 = __ldg(&g_xsw[(size_t)(j * 8 + 2 * mi + 1) * 32 + lane]);
            a[mi][0] = xv0.x;  // rows mi*16+gid
            a[mi][1] = xv1.x;  // rows mi*16+gid+8
            a[mi][2] = xv0.y;
            a[mi][3] = xv1.y;
        }

#pragma unroll
        for (int nt = 0; nt < 8; ++nt) {
            __half2 h0 = __floats2half2_rn(F0[nt].x, F0[nt].y);
            __half2 h1 = __floats2half2_rn(F1[nt].x, F1[nt].y);
            unsigned b0 = *reinterpret_cast<unsigned*>(&h0);
            unsigned b1 = *reinterpret_cast<unsigned*>(&h1);
            uint2 wout; wout.x = b0; wout.y = b1;
            g_Wsw[(size_t)(j * 64 + w * 8 + nt) * 32 + lane] = wout;  // coalesced
#pragma unroll
            for (int mi = 0; mi < 4; ++mi)
                mma16816(C[nt][mi][0], C[nt][mi][1], C[nt][mi][2], C[nt][mi][3],
                         a[mi][0], a[mi][1], a[mi][2], a[mi][3], b0, b1,
                         C[nt][mi][0], C[nt][mi][1], C[nt][mi][2], C[nt][mi][3]);
        }
    }

#pragma unroll
    for (int nt = 0; nt < 8; ++nt) {
        const int r = 64 * w + 8 * nt + 2 * tig;
#pragma unroll
        for (int mi = 0; mi < 4; ++mi) {
            const int brow = mi * 16 + gid;
            redv2(&g_spart[0][brow * ND + r], C[nt][mi][0], C[nt][mi][1]);
            redv2(&g_spart[0][(brow + 8) * ND + r], C[nt][mi][2], C[nt][mi][3]);
        }
    }
}

// ---------------------------------------------------------------------------
// Fused routing pass, 8-b blocks, 2 CTAs/SM, fully coalesced fragment loads.
// grid 592: bg = blockIdx.x & 7, cid = blockIdx.x >> 3 (j chunk of 28/26).
// MODE 1: v = squash(s0/32); MODE 2: v = squash(s0/32)+squash(s1).
// ---------------------------------------------------------------------------
template <int MODE>
__global__ void __launch_bounds__(256, 2) route_fused_kernel() {
    __shared__ float ts[2][8][36];

    const int tid = threadIdx.x;
    const int w = tid >> 5;
    const int lane = tid & 31;
    const int gid = lane >> 2;
    const int tig = lane & 3;
    const int bg = blockIdx.x & 7;
    const int cid = blockIdx.x >> 3;  // 0..73

    int jstart, rounds;
    if (cid < 62) { jstart = 28 * cid; rounds = 28; }
    else { jstart = 1736 + 26 * (cid - 62); rounds = 26; }

    const int b = bg * 8 + gid;

    // --- prologue: squash(s) -> v in registers -----------------------------
    unsigned long long vr[4][2];
#pragma unroll
    for (int q = 0; q < 4; ++q) {
        const int n = 4 * w + q;
        float vx0 = 0.f, vy0 = 0.f, vx1 = 0.f, vy1 = 0.f;
#pragma unroll
        for (int it = 0; it < MODE; ++it) {
            const float pre = (it == 0) ? (1.0f / 32.0f) : 1.0f;
            const float* sp = &g_spart[it][(b * 32 + n) * 16];
            float2 f0 = *reinterpret_cast<const float2*>(sp + 2 * tig);
            float2 f1 = *reinterpret_cast<const float2*>(sp + 8 + 2 * tig);
            f0.x *= pre; f0.y *= pre; f1.x *= pre; f1.y *= pre;
            float p = f0.x * f0.x + f0.y * f0.y + f1.x * f1.x + f1.y * f1.y;
            p += __shfl_xor_sync(0xffffffffu, p, 1);
            p += __shfl_xor_sync(0xffffffffu, p, 2);
            p += EPS;
            float sc = sqrtf(p) / (1.0f + p);
            vx0 += sc * f0.x; vy0 += sc * f0.y;
            vx1 += sc * f1.x; vy1 += sc * f1.y;
        }
        vr[q][0] = pk2(vx0, vy0);
        vr[q][1] = pk2(vx1, vy1);
    }

    unsigned long long s2[8];
#pragma unroll
    for (int nt = 0; nt < 8; ++nt) s2[nt] = 0ull;

    unsigned A0[8], A1[8], B0[8], B1[8];
    unsigned long long p01[8];

#define LOADW(jv, d0, d1)                                                      \
    {                                                                          \
        const int jc_ = (jv) > (J - 1) ? (J - 1) : (jv);                       \
        const uint2* wbase = g_Wsw + (size_t)(jc_ * 64 + w * 8) * 32 + lane;   \
        _Pragma("unroll") for (int nt = 0; nt < 8; ++nt) {                     \
            uint2 wv = __ldg(wbase + nt * 32);                                 \
            d0[nt] = wv.x;                                                     \
            d1[nt] = wv.y;                                                     \
        }                                                                      \
    }

#define PRODUCE(jv, c0, c1, n0, n1, par, DO_PF)                                \
    {                                                                          \
        const int j = (jv);                                                    \
        uint2 xv = __ldg(&g_xsw[(size_t)(j * 8 + bg) * 32 + lane]);            \
        const unsigned a0 = xv.x;                                              \
        const unsigned a2 = xv.y;                                              \
        _Pragma("unroll") for (int nt = 0; nt < 8; ++nt) {                     \
            float d0, d1, d2, d3;                                              \
            mma16816(d0, d1, d2, d3, a0, 0u, a2, 0u, c0[nt], c1[nt],           \
                     0.0f, 0.0f, 0.0f, 0.0f);                                  \
            p01[nt] = pk2(d0, d1);                                             \
        }                                                                      \
        if (DO_PF) LOADW(j + 1, n0, n1);                                       \
        float tv0[4];                                                          \
        _Pragma("unroll") for (int q = 0; q < 4; ++q) {                        \
            unsigned long long t2 = 0ull;                                      \
            fma2(t2, p01[2 * q], vr[q][0]);                                    \
            fma2(t2, p01[2 * q + 1], vr[q][1]);                                \
            float2 f = upk2(t2);                                               \
            float tt = f.x + f.y;                                              \
            tt += __shfl_xor_sync(0xffffffffu, tt, 1);                         \
            tt += __shfl_xor_sync(0xffffffffu, tt, 2);                         \
            tv0[q] = tt;                                                       \
        }                                                                      \
        float e0 = __expf(tig == 0 ? tv0[0] : tig == 1 ? tv0[1]                \
                                  : tig == 2 ? tv0[2] : tv0[3]);               \
        ts[par][gid][4 * w + tig] = e0;                                        \
    }

#define CONSUME(par)                                                           \
    {                                                                          \
        float4 sa0 = *reinterpret_cast<const float4*>(&ts[par][gid][tig * 8]); \
        float4 sa1 = *reinterpret_cast<const float4*>(&ts[par][gid][tig * 8 + 4]);\
        float SA = sa0.x + sa0.y + sa0.z + sa0.w + sa1.x + sa1.y + sa1.z + sa1.w;\
        SA += __shfl_xor_sync(0xffffffffu, SA, 1);                             \
        SA += __shfl_xor_sync(0xffffffffu, SA, 2);                             \
        float rA = __fdividef(1.0f, SA);                                       \
        float4 eA = *reinterpret_cast<const float4*>(&ts[par][gid][4 * w]);    \
        const float cAa[4] = {eA.x * rA, eA.y * rA, eA.z * rA, eA.w * rA};     \
        _Pragma("unroll") for (int nt = 0; nt < 8; ++nt) {                     \
            const int q = nt >> 1;                                             \
            fma2(s2[nt], pk2(cAa[q], cAa[q]), p01[nt]);                        \
        }                                                                      \
    }

    LOADW(jstart, A0, A1);
    for (int rd = 0; rd < rounds; rd += 2) {
        PRODUCE(jstart + rd, A0, A1, B0, B1, 0, 1);
        __syncthreads();
        CONSUME(0);
        PRODUCE(jstart + rd + 1, B0, B1, A0, A1, 1, (rd + 2 < rounds));
        __syncthreads();
        CONSUME(1);
    }
#undef PRODUCE
#undef CONSUME
#undef LOADW

    // flush s partials
#pragma unroll
    for (int nt = 0; nt < 8; ++nt) {
        const int r = 64 * w + 8 * nt + 2 * tig;
        float2 fa = upk2(s2[nt]);
        redv2(&g_spart[MODE][b * ND + r], fa.x, fa.y);
    }
}

// ---------------------------------------------------------------------------
__global__ void squash_out_kernel(float* __restrict__ out) {
    int t = blockIdx.x * blockDim.x + threadIdx.x;  // (b*32+n)
    const float* s = &g_spart[2][t * 16];
    float sv[16];
    float s2 = 0.0f;
#pragma unroll
    for (int d = 0; d < 16; ++d) {
        float val = s[d];
        sv[d] = val;
        s2 = fmaf(val, val, s2);
    }
    s2 += EPS;
    float sc = sqrtf(s2) / (1.0f + s2);
#pragma unroll
    for (int d = 0; d < 16; ++d) out[t * 16 + d] = sc * sv[d];
}

// ---------------------------------------------------------------------------
extern "C" void kernel_launch(void* const* d_in, const int* in_sizes, int n_in,
                              void* d_out, int out_size) {
    const float* x = (const float*)d_in[0];  // [B, J, 16]
    const float* W = (const float*)d_in[1];  // [N, J, D, 16]
    float* out = (float*)d_out;              // [B, N, D]

    cvt_x_zero_kernel<<<2048, 256>>>(x);
    k_s0cvt_kernel<<<256, 256>>>(W);
    route_fused_kernel<1><<<592, 256>>>();
    route_fused_kernel<2><<<592, 256>>>();
    squash_out_kernel<<<16, 128>>>(out);
}

// round 9
// speedup vs baseline: 1.2867x; 1.0109x over previous
#include <cuda_runtime.h>
#include <cuda_fp16.h>
#include <math.h>

#define B 64
#define J 2048
#define N 32
#define D 16
#define ND 512
#define EPS 1e-7f

// Swizzled fragment storage:
// g_Wsw[(j*64 + w*8 + nt)*32 + lane] = uint2{b0,b1} for r = 64w+8nt+gid, tig
__device__ __align__(16) uint2 g_Wsw[(size_t)J * 64 * 32];   // 33.5 MiB
// g_xsw[(j*8 + bg)*32 + lane] = uint2{a0,a2} for b = bg*8+gid, tig
__device__ __align__(16) uint2 g_xsw[(size_t)J * 8 * 32];    // 4.2 MiB
__device__ __align__(16) float g_spart[3][B * ND];           // s accum [b][n*16+d]

// ---- helpers --------------------------------------------------------------
static __device__ __forceinline__ unsigned long long pk2(float a, float b) {
    unsigned long long v;
    asm("mov.b64 %0, {%1, %2};" : "=l"(v) : "f"(a), "f"(b));
    return v;
}
static __device__ __forceinline__ float2 upk2(unsigned long long v) {
    float2 f;
    asm("mov.b64 {%0, %1}, %2;" : "=f"(f.x), "=f"(f.y) : "l"(v));
    return f;
}
static __device__ __forceinline__ void fma2(unsigned long long& d,
                                            unsigned long long a,
                                            unsigned long long b) {
    asm("fma.rn.f32x2 %0, %1, %2, %0;" : "+l"(d) : "l"(a), "l"(b));
}
static __device__ __forceinline__ void redv2(float* p, float a, float b) {
    asm volatile("red.global.add.v2.f32 [%0], {%1, %2};"
                 :: "l"(p), "f"(a), "f"(b) : "memory");
}
static __device__ __forceinline__ void mma16816(
    float& d0, float& d1, float& d2, float& d3,
    unsigned a0, unsigned a1, unsigned a2, unsigned a3,
    unsigned b0, unsigned b1,
    float c0, float c1, float c2, float c3) {
    asm volatile(
        "mma.sync.aligned.m16n8k16.row.col.f32.f16.f16.f32 "
        "{%0,%1,%2,%3},{%4,%5,%6,%7},{%8,%9},{%10,%11,%12,%13};"
        : "=f"(d0), "=f"(d1), "=f"(d2), "=f"(d3)
        : "r"(a0), "r"(a1), "r"(a2), "r"(a3), "r"(b0), "r"(b1),
          "f"(c0), "f"(c1), "f"(c2), "f"(c3));
}

// ---------------------------------------------------------------------------
__global__ void cvt_x_zero_kernel(const float* __restrict__ x) {
    int o = blockIdx.x * blockDim.x + threadIdx.x;  // < 524288
    const int lane = o & 31;
    const int bg = (o >> 5) & 7;
    const int j = o >> 8;
    const int tig = lane & 3;
    const int gid = lane >> 2;
    const int b = bg * 8 + gid;

    const float* xp = x + ((size_t)(b * J + j) << 4);
    float2 f0 = *reinterpret_cast<const float2*>(xp + 2 * tig);
    float2 f1 = *reinterpret_cast<const float2*>(xp + 2 * tig + 8);
    __half2 h0 = __floats2half2_rn(f0.x, f0.y);
    __half2 h1 = __floats2half2_rn(f1.x, f1.y);
    uint2 out;
    out.x = *reinterpret_cast<unsigned*>(&h0);
    out.y = *reinterpret_cast<unsigned*>(&h1);
    g_xsw[o] = out;

    if (o < 3 * B * ND) ((float*)g_spart)[o] = 0.0f;
}

// ---------------------------------------------------------------------------
// k_s0cvt: stream W fp32 -> fp16 swizzled fragments (coalesced store),
// mma-accumulate s0. grid 256 (jtile 8), 256 thr / 8 warps.
// ---------------------------------------------------------------------------
__global__ void __launch_bounds__(256, 1)
k_s0cvt_kernel(const float* __restrict__ Wf) {
    const int tid = threadIdx.x;
    const int w = tid >> 5;
    const int lane = tid & 31;
    const int gid = lane >> 2;
    const int tig = lane & 3;

    float C[8][4][4];
#pragma unroll
    for (int nt = 0; nt < 8; ++nt)
#pragma unroll
        for (int mi = 0; mi < 4; ++mi)
#pragma unroll
            for (int e = 0; e < 4; ++e) C[nt][mi][e] = 0.0f;

    for (int jj = 0; jj < 8; ++jj) {
        const int j = blockIdx.x * 8 + jj;

        float2 F0[8], F1[8];
#pragma unroll
        for (int nt = 0; nt < 8; ++nt) {
            const int r = 64 * w + 8 * nt + gid;
            const float* wp = Wf + ((size_t)((r >> 4) * J + j)) * 256 + ((r & 15) << 4);
            F0[nt] = *reinterpret_cast<const float2*>(wp + 2 * tig);
            F1[nt] = *reinterpret_cast<const float2*>(wp + 2 * tig + 8);
        }

        unsigned a[4][4];
#pragma unroll
        for (int mi = 0; mi < 4; ++mi) {
            uint2 xv0 = __ldg(&g_xsw[(size_t)(j * 8 + 2 * mi) * 32 + lane]);
            uint2 xv1 = __ldg(&g_xsw[(size_t)(j * 8 + 2 * mi + 1) * 32 + lane]);
            a[mi][0] = xv0.x;
            a[mi][1] = xv1.x;
            a[mi][2] = xv0.y;
            a[mi][3] = xv1.y;
        }

#pragma unroll
        for (int nt = 0; nt < 8; ++nt) {
            __half2 h0 = __floats2half2_rn(F0[nt].x, F0[nt].y);
            __half2 h1 = __floats2half2_rn(F1[nt].x, F1[nt].y);
            unsigned b0 = *reinterpret_cast<unsigned*>(&h0);
            unsigned b1 = *reinterpret_cast<unsigned*>(&h1);
            uint2 wout; wout.x = b0; wout.y = b1;
            g_Wsw[(size_t)(j * 64 + w * 8 + nt) * 32 + lane] = wout;
#pragma unroll
            for (int mi = 0; mi < 4; ++mi)
                mma16816(C[nt][mi][0], C[nt][mi][1], C[nt][mi][2], C[nt][mi][3],
                         a[mi][0], a[mi][1], a[mi][2], a[mi][3], b0, b1,
                         C[nt][mi][0], C[nt][mi][1], C[nt][mi][2], C[nt][mi][3]);
        }
    }

#pragma unroll
    for (int nt = 0; nt < 8; ++nt) {
        const int r = 64 * w + 8 * nt + 2 * tig;
#pragma unroll
        for (int mi = 0; mi < 4; ++mi) {
            const int brow = mi * 16 + gid;
            redv2(&g_spart[0][brow * ND + r], C[nt][mi][0], C[nt][mi][1]);
            redv2(&g_spart[0][(brow + 8) * ND + r], C[nt][mi][2], C[nt][mi][3]);
        }
    }
}

// ---------------------------------------------------------------------------
// Fused routing pass, 8-b blocks, 2 CTAs/SM, deferred-consume pipeline:
// per round: LOADW(j) issued -> CONSUME(j-1) in the load shadow -> PRODUCE(j)
// -> one BAR. p01/ts double-buffered by parity.
// ---------------------------------------------------------------------------
template <int MODE>
__global__ void __launch_bounds__(256, 2) route_fused_kernel() {
    __shared__ float ts[2][8][36];

    const int tid = threadIdx.x;
    const int w = tid >> 5;
    const int lane = tid & 31;
    const int gid = lane >> 2;
    const int tig = lane & 3;
    const int bg = blockIdx.x & 7;
    const int cid = blockIdx.x >> 3;  // 0..73

    int jstart, rounds;
    if (cid < 62) { jstart = 28 * cid; rounds = 28; }
    else { jstart = 1736 + 26 * (cid - 62); rounds = 26; }

    const int b = bg * 8 + gid;

    // --- prologue: squash(s) -> v in registers -----------------------------
    unsigned long long vr[4][2];
#pragma unroll
    for (int q = 0; q < 4; ++q) {
        const int n = 4 * w + q;
        float vx0 = 0.f, vy0 = 0.f, vx1 = 0.f, vy1 = 0.f;
#pragma unroll
        for (int it = 0; it < MODE; ++it) {
            const float pre = (it == 0) ? (1.0f / 32.0f) : 1.0f;
            const float* sp = &g_spart[it][(b * 32 + n) * 16];
            float2 f0 = *reinterpret_cast<const float2*>(sp + 2 * tig);
            float2 f1 = *reinterpret_cast<const float2*>(sp + 8 + 2 * tig);
            f0.x *= pre; f0.y *= pre; f1.x *= pre; f1.y *= pre;
            float p = f0.x * f0.x + f0.y * f0.y + f1.x * f1.x + f1.y * f1.y;
            p += __shfl_xor_sync(0xffffffffu, p, 1);
            p += __shfl_xor_sync(0xffffffffu, p, 2);
            p += EPS;
            float sc = sqrtf(p) / (1.0f + p);
            vx0 += sc * f0.x; vy0 += sc * f0.y;
            vx1 += sc * f1.x; vy1 += sc * f1.y;
        }
        vr[q][0] = pk2(vx0, vy0);
        vr[q][1] = pk2(vx1, vy1);
    }

    unsigned long long s2[8];
#pragma unroll
    for (int nt = 0; nt < 8; ++nt) s2[nt] = 0ull;

    unsigned W0[8], W1[8];
    uint2 xv;
    unsigned long long p01a[8], p01b[8];

// Issue x + W fragment loads for round j (coalesced; values land in xv/W0/W1)
#define LOADWX(jv)                                                             \
    {                                                                          \
        xv = __ldg(&g_xsw[(size_t)((jv) * 8 + bg) * 32 + lane]);               \
        const uint2* wb = g_Wsw + (size_t)((jv) * 64 + w * 8) * 32 + lane;     \
        _Pragma("unroll") for (int nt = 0; nt < 8; ++nt) {                     \
            uint2 wv = __ldg(wb + nt * 32);                                    \
            W0[nt] = wv.x;                                                     \
            W1[nt] = wv.y;                                                     \
        }                                                                      \
    }

#define PRODUCE(par, P)                                                        \
    {                                                                          \
        const unsigned a0 = xv.x;                                              \
        const unsigned a2 = xv.y;                                              \
        _Pragma("unroll") for (int nt = 0; nt < 8; ++nt) {                     \
            float d0, d1, d2, d3;                                              \
            mma16816(d0, d1, d2, d3, a0, 0u, a2, 0u, W0[nt], W1[nt],           \
                     0.0f, 0.0f, 0.0f, 0.0f);                                  \
            P[nt] = pk2(d0, d1);                                               \
        }                                                                      \
        float tv0[4];                                                          \
        _Pragma("unroll") for (int q = 0; q < 4; ++q) {                        \
            unsigned long long t2 = 0ull;                                      \
            fma2(t2, P[2 * q], vr[q][0]);                                      \
            fma2(t2, P[2 * q + 1], vr[q][1]);                                  \
            float2 f = upk2(t2);                                               \
            float tt = f.x + f.y;                                              \
            tt += __shfl_xor_sync(0xffffffffu, tt, 1);                         \
            tt += __shfl_xor_sync(0xffffffffu, tt, 2);                         \
            tv0[q] = tt;                                                       \
        }                                                                      \
        float e0 = __expf(tig == 0 ? tv0[0] : tig == 1 ? tv0[1]                \
                                  : tig == 2 ? tv0[2] : tv0[3]);               \
        ts[par][gid][4 * w + tig] = e0;                                        \
    }

#define CONSUME(par, P)                                                        \
    {                                                                          \
        float4 sa0 = *reinterpret_cast<const float4*>(&ts[par][gid][tig * 8]); \
        float4 sa1 = *reinterpret_cast<const float4*>(&ts[par][gid][tig * 8 + 4]);\
        float SA = sa0.x + sa0.y + sa0.z + sa0.w + sa1.x + sa1.y + sa1.z + sa1.w;\
        SA += __shfl_xor_sync(0xffffffffu, SA, 1);                             \
        SA += __shfl_xor_sync(0xffffffffu, SA, 2);                             \
        float rA = __fdividef(1.0f, SA);                                       \
        float4 eA = *reinterpret_cast<const float4*>(&ts[par][gid][4 * w]);    \
        const float cAa[4] = {eA.x * rA, eA.y * rA, eA.z * rA, eA.w * rA};     \
        _Pragma("unroll") for (int nt = 0; nt < 8; ++nt) {                     \
            const int q = nt >> 1;                                             \
            fma2(s2[nt], pk2(cAa[q], cAa[q]), P[nt]);                          \
        }                                                                      \
    }

    // pipeline: round rd: LOADWX(j_rd) -> CONSUME(rd-1) in shadow -> PRODUCE -> BAR
    LOADWX(jstart);
    PRODUCE(0, p01a);
    __syncthreads();
    for (int rd = 1; rd + 1 < rounds; rd += 2) {
        LOADWX(jstart + rd);
        CONSUME(0, p01a);
        PRODUCE(1, p01b);
        __syncthreads();
        LOADWX(jstart + rd + 1);
        CONSUME(1, p01b);
        PRODUCE(0, p01a);
        __syncthreads();
    }
    // rounds is even: one odd round remains (rd = rounds-1)
    LOADWX(jstart + rounds - 1);
    CONSUME(0, p01a);
    PRODUCE(1, p01b);
    __syncthreads();
    CONSUME(1, p01b);
#undef PRODUCE
#undef CONSUME
#undef LOADWX

    // flush s partials
#pragma unroll
    for (int nt = 0; nt < 8; ++nt) {
        const int r = 64 * w + 8 * nt + 2 * tig;
        float2 fa = upk2(s2[nt]);
        redv2(&g_spart[MODE][b * ND + r], fa.x, fa.y);
    }
}

// ---------------------------------------------------------------------------
__global__ void squash_out_kernel(float* __restrict__ out) {
    int t = blockIdx.x * blockDim.x + threadIdx.x;  // (b*32+n)
    const float* s = &g_spart[2][t * 16];
    float sv[16];
    float s2 = 0.0f;
#pragma unroll
    for (int d = 0; d < 16; ++d) {
        float val = s[d];
        sv[d] = val;
        s2 = fmaf(val, val, s2);
    }
    s2 += EPS;
    float sc = sqrtf(s2) / (1.0f + s2);
#pragma unroll
    for (int d = 0; d < 16; ++d) out[t * 16 + d] = sc * sv[d];
}

// ---------------------------------------------------------------------------
extern "C" void kernel_launch(void* const* d_in, const int* in_sizes, int n_in,
                              void* d_out, int out_size) {
    const float* x = (const float*)d_in[0];  // [B, J, 16]
    const float* W = (const float*)d_in[1];  // [N, J, D, 16]
    float* out = (float*)d_out;              // [B, N, D]

    cvt_x_zero_kernel<<<2048, 256>>>(x);
    k_s0cvt_kernel<<<256, 256>>>(W);
    route_fused_kernel<1><<<592, 256>>>();
    route_fused_kernel<2><<<592, 256>>>();
    squash_out_kernel<<<16, 128>>>(out);
}